// round 8
// baseline (speedup 1.0000x reference)
#include <cuda_runtime.h>
#include <cstdint>

#define NODES 100000
#define FDIM  128
#define NCLS  40
#define EMAX  1700000

// Scratch (allocation-free rule: __device__ globals)
__device__ float g_agg[(size_t)NODES * FDIM];
__device__ float g_x1 [(size_t)NODES * FDIM];
__device__ float g_x2 [(size_t)NODES * FDIM];
__device__ int   g_deg[NODES];
__device__ int   g_cursor[NODES];
__device__ int   g_off[NODES + 1];
__device__ int   g_csr[EMAX];

// Packed fp32x2 FMA (sm_100+): d = a*b + c on both 32-bit halves. FFMA2 in SASS.
#define FMA2(d, a, b, c) \
    asm("fma.rn.f32x2 %0, %1, %2, %3;" : "=l"(d) : "l"(a), "l"(b), "l"(c))

__device__ __forceinline__ unsigned long long pack2(float lo, float hi) {
    unsigned long long r;
    asm("mov.b64 %0, {%1, %2};" : "=l"(r) : "r"(__float_as_uint(lo)), "r"(__float_as_uint(hi)));
    return r;
}
__device__ __forceinline__ void unpack2(unsigned long long p, float& lo, float& hi) {
    unsigned int a, b;
    asm("mov.b64 {%0, %1}, %2;" : "=r"(a), "=r"(b) : "l"(p));
    lo = __uint_as_float(a); hi = __uint_as_float(b);
}

// ---------------------------------------------------------------------------
// CSR build
// ---------------------------------------------------------------------------
__global__ void __launch_bounds__(256) hist_kernel(
    const int* __restrict__ dst, int* __restrict__ deg, int E)
{
    int e = blockIdx.x * blockDim.x + threadIdx.x;
    if (e < E) atomicAdd(&deg[__ldg(dst + e)], 1);
}

__global__ void __launch_bounds__(1024) scan_kernel(
    const int* __restrict__ deg, int* __restrict__ off, int n)
{
    __shared__ int wsum[32];
    __shared__ int blocktot;
    int tid = threadIdx.x, lane = tid & 31, wid = tid >> 5;
    int running = 0;

    for (int base = 0; base < n; base += 1024) {
        int idx = base + tid;
        int v = (idx < n) ? deg[idx] : 0;
        int s = v;
        #pragma unroll
        for (int o = 1; o < 32; o <<= 1) {
            int t = __shfl_up_sync(0xffffffffu, s, o);
            if (lane >= o) s += t;
        }
        if (lane == 31) wsum[wid] = s;
        __syncthreads();
        if (wid == 0) {
            int ws = wsum[lane];
            int ss = ws;
            #pragma unroll
            for (int o = 1; o < 32; o <<= 1) {
                int t = __shfl_up_sync(0xffffffffu, ss, o);
                if (lane >= o) ss += t;
            }
            if (lane == 31) blocktot = ss;
            wsum[lane] = ss - ws;
        }
        __syncthreads();
        int excl = running + wsum[wid] + (s - v);
        if (idx < n) off[idx] = excl;
        running += blocktot;
        __syncthreads();
    }
    if (tid == 0) off[n] = running;
}

__global__ void __launch_bounds__(256) fill_kernel(
    const int* __restrict__ src, const int* __restrict__ dst,
    const int* __restrict__ off, int* __restrict__ cursor,
    int* __restrict__ csr, int E)
{
    int e = blockIdx.x * blockDim.x + threadIdx.x;
    if (e >= E) return;
    int d = __ldg(dst + e);
    int pos = atomicAdd(&cursor[d], 1);
    csr[__ldg(off + d) + pos] = __ldg(src + e);
}

// ---------------------------------------------------------------------------
// Gather aggregation (unchanged — near L2 bound)
// ---------------------------------------------------------------------------
__global__ void __launch_bounds__(256) gather_kernel(
    const float* __restrict__ x,
    const int* __restrict__ off, const int* __restrict__ csr,
    float* __restrict__ agg)
{
    int node = (blockIdx.x * blockDim.x + threadIdx.x) >> 5;
    int lane = threadIdx.x & 31;
    if (node >= NODES) return;
    int lo = __ldg(off + node), hi = __ldg(off + node + 1);

    float4 a = make_float4(0.f, 0.f, 0.f, 0.f);
    int i = lo;
    for (; i + 1 < hi; i += 2) {
        int s0 = __ldg(csr + i);
        int s1 = __ldg(csr + i + 1);
        float4 v0 = *reinterpret_cast<const float4*>(x + (size_t)s0 * FDIM + lane * 4);
        float4 v1 = *reinterpret_cast<const float4*>(x + (size_t)s1 * FDIM + lane * 4);
        a.x += v0.x + v1.x; a.y += v0.y + v1.y;
        a.z += v0.z + v1.z; a.w += v0.w + v1.w;
    }
    if (i < hi) {
        int s0 = __ldg(csr + i);
        float4 v0 = *reinterpret_cast<const float4*>(x + (size_t)s0 * FDIM + lane * 4);
        a.x += v0.x; a.y += v0.y; a.z += v0.z; a.w += v0.w;
    }
    *reinterpret_cast<float4*>(agg + (size_t)node * FDIM + lane * 4) = a;
}

// ---------------------------------------------------------------------------
// Fused GraphConv with FFMA2: out = relu(agg @ W_rel + xin @ W_root + b)
// Activations stored as DUPLICATED pairs in smem so one LDS.64 broadcast
// yields a packed f32x2 operand; weight pairs read directly as ulonglong2.
// ---------------------------------------------------------------------------
__global__ void __launch_bounds__(256) conv_kernel(
    const float* __restrict__ xin, const float* __restrict__ agg,
    const float* __restrict__ Wrel, const float* __restrict__ Wroot,
    const float* __restrict__ bias, float* __restrict__ out)
{
    __shared__ float sWr[32][128];
    __shared__ float sWo[32][128];
    __shared__ float sX2[64][64];   // dup pairs: [n][2k]=[n][2k+1]=x[n][kt+k]
    __shared__ float sA2[64][64];

    int tid = threadIdx.x;
    int tx  = tid & 31;
    int ty  = tid >> 5;
    int f0  = tx * 4;
    int nodeBase = blockIdx.x * 64;

    float4 bv = *reinterpret_cast<const float4*>(bias + f0);
    unsigned long long acc[8][2];
    {
        unsigned long long b0 = pack2(bv.x, bv.y);
        unsigned long long b1 = pack2(bv.z, bv.w);
        #pragma unroll
        for (int n = 0; n < 8; n++) { acc[n][0] = b0; acc[n][1] = b1; }
    }

    for (int kt = 0; kt < FDIM; kt += 32) {
        #pragma unroll
        for (int i = tid; i < 1024; i += 256) {
            int kk = i >> 5;
            int fq = (i & 31) * 4;
            *reinterpret_cast<float4*>(&sWr[kk][fq]) =
                *reinterpret_cast<const float4*>(Wrel + (size_t)(kt + kk) * FDIM + fq);
            *reinterpret_cast<float4*>(&sWo[kk][fq]) =
                *reinterpret_cast<const float4*>(Wroot + (size_t)(kt + kk) * FDIM + fq);
        }
        #pragma unroll
        for (int i = tid; i < 512; i += 256) {
            int n  = i >> 3;
            int kq = (i & 7) * 4;
            int node = nodeBase + n;
            float4 xv = make_float4(0.f, 0.f, 0.f, 0.f);
            float4 av = xv;
            if (node < NODES) {
                xv = *reinterpret_cast<const float4*>(xin + (size_t)node * FDIM + kt + kq);
                av = *reinterpret_cast<const float4*>(agg + (size_t)node * FDIM + kt + kq);
            }
            *reinterpret_cast<float4*>(&sX2[n][2 * kq])     = make_float4(xv.x, xv.x, xv.y, xv.y);
            *reinterpret_cast<float4*>(&sX2[n][2 * kq + 4]) = make_float4(xv.z, xv.z, xv.w, xv.w);
            *reinterpret_cast<float4*>(&sA2[n][2 * kq])     = make_float4(av.x, av.x, av.y, av.y);
            *reinterpret_cast<float4*>(&sA2[n][2 * kq + 4]) = make_float4(av.z, av.z, av.w, av.w);
        }
        __syncthreads();

        #pragma unroll 4
        for (int kk = 0; kk < 32; kk++) {
            ulonglong2 wr = *reinterpret_cast<const ulonglong2*>(&sWr[kk][f0]);
            ulonglong2 wo = *reinterpret_cast<const ulonglong2*>(&sWo[kk][f0]);
            #pragma unroll
            for (int n = 0; n < 8; n++) {
                unsigned long long xv =
                    *reinterpret_cast<const unsigned long long*>(&sX2[ty * 8 + n][2 * kk]);
                unsigned long long av =
                    *reinterpret_cast<const unsigned long long*>(&sA2[ty * 8 + n][2 * kk]);
                unsigned long long t0, t1;
                FMA2(t0, xv, wo.x, acc[n][0]);
                FMA2(acc[n][0], av, wr.x, t0);
                FMA2(t1, xv, wo.y, acc[n][1]);
                FMA2(acc[n][1], av, wr.y, t1);
            }
        }
        __syncthreads();
    }

    #pragma unroll
    for (int n = 0; n < 8; n++) {
        int node = nodeBase + ty * 8 + n;
        if (node < NODES) {
            float a0, a1, a2, a3;
            unpack2(acc[n][0], a0, a1);
            unpack2(acc[n][1], a2, a3);
            float4 o;
            o.x = fmaxf(a0, 0.f); o.y = fmaxf(a1, 0.f);
            o.z = fmaxf(a2, 0.f); o.w = fmaxf(a3, 0.f);
            *reinterpret_cast<float4*>(out + (size_t)node * FDIM + f0) = o;
        }
    }
}

// ---------------------------------------------------------------------------
// Classifier with FFMA2: out = log_softmax([x1|x2] @ W_lin + b_lin)
// W_lin transposed into smem sWt[c][k] (row padded to 258 for 8B alignment);
// k-dimension processed in packed pairs. Accumulator halves summed at end.
// ---------------------------------------------------------------------------
#define WTP 258
__global__ void __launch_bounds__(128) cls_kernel(
    const float* __restrict__ x1, const float* __restrict__ x2,
    const float* __restrict__ Wlin, const float* __restrict__ blin,
    float* __restrict__ out, int nGroupsStride)
{
    __shared__ float sWt[NCLS][WTP];        // transposed W_lin, ~41KB
    __shared__ float sb[NCLS];
    __shared__ float sH[4][4][2 * FDIM];    // 16KB

    int tid = threadIdx.x;
    for (int i = tid; i < 2 * FDIM * NCLS; i += 128) {
        int k = i / NCLS, c = i % NCLS;
        sWt[c][k] = Wlin[i];
    }
    if (tid < NCLS) sb[tid] = blin[tid];
    __syncthreads();

    int wid  = tid >> 5;
    int lane = tid & 31;
    int l8   = lane & 7;
    unsigned long long bias0 = pack2(sb[lane], 0.f);
    unsigned long long bias1 = pack2(sb[32 + l8], 0.f);

    const int nGroups = (NODES + 3) / 4;
    for (int g = blockIdx.x * 4 + wid; g < nGroups; g += nGroupsStride) {
        int n0 = g * 4;
        #pragma unroll
        for (int j = 0; j < 4; j++) {
            int node = n0 + j; if (node >= NODES) node = NODES - 1;
            reinterpret_cast<float4*>(sH[wid][j])[lane] =
                reinterpret_cast<const float4*>(x1 + (size_t)node * FDIM)[lane];
            reinterpret_cast<float4*>(sH[wid][j])[32 + lane] =
                reinterpret_cast<const float4*>(x2 + (size_t)node * FDIM)[lane];
        }
        __syncwarp();

        unsigned long long v0a[4], v1a[4];
        #pragma unroll
        for (int j = 0; j < 4; j++) { v0a[j] = bias0; v1a[j] = bias1; }

        #pragma unroll 4
        for (int k2 = 0; k2 < FDIM; k2++) {   // 128 k-pairs over 2*FDIM
            unsigned long long w0p =
                *reinterpret_cast<const unsigned long long*>(&sWt[lane][2 * k2]);
            unsigned long long w1p =
                *reinterpret_cast<const unsigned long long*>(&sWt[32 + l8][2 * k2]);
            #pragma unroll
            for (int j = 0; j < 4; j++) {
                unsigned long long hp =
                    *reinterpret_cast<const unsigned long long*>(&sH[wid][j][2 * k2]);
                FMA2(v0a[j], hp, w0p, v0a[j]);
                FMA2(v1a[j], hp, w1p, v1a[j]);
            }
        }

        #pragma unroll
        for (int j = 0; j < 4; j++) {
            int node = n0 + j;
            float e0, o0, e1, o1;
            unpack2(v0a[j], e0, o0);
            unpack2(v1a[j], e1, o1);
            float v0 = e0 + o0;
            float v1 = e1 + o1;

            float m = fmaxf(v0, v1);
            #pragma unroll
            for (int off = 16; off; off >>= 1)
                m = fmaxf(m, __shfl_xor_sync(0xffffffffu, m, off));
            float s = __expf(v0 - m) + ((lane < 8) ? __expf(v1 - m) : 0.f);
            #pragma unroll
            for (int off = 16; off; off >>= 1)
                s += __shfl_xor_sync(0xffffffffu, s, off);
            float lse = m + __logf(s);
            if (node < NODES) {
                out[(size_t)node * NCLS + lane] = v0 - lse;
                if (lane < 8) out[(size_t)node * NCLS + 32 + lane] = v1 - lse;
            }
        }
        __syncwarp();
    }
}

// ---------------------------------------------------------------------------
extern "C" void kernel_launch(void* const* d_in, const int* in_sizes, int n_in,
                              void* d_out, int out_size)
{
    const float* x      = (const float*)d_in[0];
    const int*   eidx   = (const int*)  d_in[1];
    const float* Wrel1  = (const float*)d_in[2];
    const float* b1     = (const float*)d_in[3];
    const float* Wroot1 = (const float*)d_in[4];
    const float* Wrel2  = (const float*)d_in[5];
    const float* b2     = (const float*)d_in[6];
    const float* Wroot2 = (const float*)d_in[7];
    const float* Wlin   = (const float*)d_in[8];
    const float* blin   = (const float*)d_in[9];
    float* out = (float*)d_out;

    int E = in_sizes[1] / 2;
    const int* src = eidx;
    const int* dst = eidx + E;

    float *agg, *x1, *x2;
    int *deg, *cursor, *off, *csr;
    cudaGetSymbolAddress((void**)&agg,    g_agg);
    cudaGetSymbolAddress((void**)&x1,     g_x1);
    cudaGetSymbolAddress((void**)&x2,     g_x2);
    cudaGetSymbolAddress((void**)&deg,    g_deg);
    cudaGetSymbolAddress((void**)&cursor, g_cursor);
    cudaGetSymbolAddress((void**)&off,    g_off);
    cudaGetSymbolAddress((void**)&csr,    g_csr);

    int eblocks = (E + 255) / 256;
    int gblocks = (NODES * 32 + 255) / 256;
    int cblocks = (NODES + 63) / 64;

    // --- CSR build ---
    cudaMemsetAsync(deg,    0, NODES * sizeof(int), 0);
    cudaMemsetAsync(cursor, 0, NODES * sizeof(int), 0);
    hist_kernel<<<eblocks, 256>>>(dst, deg, E);
    scan_kernel<<<1, 1024>>>(deg, off, NODES);
    fill_kernel<<<eblocks, 256>>>(src, dst, off, cursor, csr, E);

    // --- Layer 1 ---
    gather_kernel<<<gblocks, 256>>>(x, off, csr, agg);
    conv_kernel<<<cblocks, 256>>>(x, agg, Wrel1, Wroot1, b1, x1);

    // --- Layer 2 ---
    gather_kernel<<<gblocks, 256>>>(x1, off, csr, agg);
    conv_kernel<<<cblocks, 256>>>(x1, agg, Wrel2, Wroot2, b2, x2);

    // --- Classifier + log_softmax ---
    int clsBlocks = 592;
    cls_kernel<<<clsBlocks, 128>>>(x1, x2, Wlin, blin, out, clsBlocks * 4);
}

// round 10
// speedup vs baseline: 1.8839x; 1.8839x over previous
#include <cuda_runtime.h>
#include <cuda_bf16.h>
#include <cstdint>

#define NODES 100000
#define FDIM  128
#define NCLS  40
#define EMAX  1700000

// Scratch (allocation-free rule: __device__ globals)
__device__ float g_agg[(size_t)NODES * FDIM];
__device__ float g_x1 [(size_t)NODES * FDIM];
__device__ float g_x2 [(size_t)NODES * FDIM];
__device__ int   g_deg[NODES];
__device__ int   g_cursor[NODES];
__device__ int   g_off[NODES + 1];
__device__ int   g_csr[EMAX];
// Transposed bf16 weight images: B[layer][f][k] = W_cat[k][f], hi/lo split.
// W_cat = [Wrel ; Wroot] (K = 256).
__device__ __nv_bfloat16 g_Bhi[2][FDIM][256];
__device__ __nv_bfloat16 g_Blo[2][FDIM][256];

// ---------------------------------------------------------------------------
// Weight prep: transpose + bf16 hi/lo split.
// ---------------------------------------------------------------------------
__global__ void __launch_bounds__(256) prep_kernel(
    const float* __restrict__ Wrel1, const float* __restrict__ Wroot1,
    const float* __restrict__ Wrel2, const float* __restrict__ Wroot2)
{
    int i = blockIdx.x * blockDim.x + threadIdx.x;   // 2 * 256 * 128
    if (i >= 2 * 256 * 128) return;
    int l = i >> 15;
    int r = i & 32767;
    int k = r >> 7;          // 0..255
    int f = r & 127;         // 0..127
    const float* Wrel  = l ? Wrel2  : Wrel1;
    const float* Wroot = l ? Wroot2 : Wroot1;
    float w = (k < 128) ? Wrel[k * 128 + f] : Wroot[(k - 128) * 128 + f];
    __nv_bfloat16 hi = __float2bfloat16(w);
    __nv_bfloat16 lo = __float2bfloat16(w - __bfloat162float(hi));
    g_Bhi[l][f][k] = hi;
    g_Blo[l][f][k] = lo;
}

// ---------------------------------------------------------------------------
// Tensor-core GraphConv via mma.sync (m16n8k16 bf16, fp32 accum), 3-pass
// bf16 split for fp32-grade precision.
// CTA: 128 nodes x 128 feats. 8 warps: warp tile 64(M) x 32(N).
// K = 256 = concat [agg | xin] @ [Wrel ; Wroot], in 8 chunks of 32.
// ---------------------------------------------------------------------------
#define KCH   32
#define APIT  (KCH + 2)    // smem pitch in bf16 elems (68B rows, conflict-broken)

__device__ __forceinline__ void mma16816(float* d, const uint32_t* a,
                                         const uint32_t* b) {
    asm volatile(
        "mma.sync.aligned.m16n8k16.row.col.f32.bf16.bf16.f32 "
        "{%0,%1,%2,%3}, {%4,%5,%6,%7}, {%8,%9}, {%0,%1,%2,%3};"
        : "+f"(d[0]), "+f"(d[1]), "+f"(d[2]), "+f"(d[3])
        : "r"(a[0]), "r"(a[1]), "r"(a[2]), "r"(a[3]), "r"(b[0]), "r"(b[1]));
}

__global__ void __launch_bounds__(256) conv_kernel(
    const float* __restrict__ xin, const float* __restrict__ agg,
    const float* __restrict__ bias, float* __restrict__ out, int layer)
{
    __shared__ __nv_bfloat16 sAhi[128][APIT];
    __shared__ __nv_bfloat16 sAlo[128][APIT];
    __shared__ __nv_bfloat16 sBhi[128][APIT];
    __shared__ __nv_bfloat16 sBlo[128][APIT];
    __shared__ float sBias[FDIM];

    int tid  = threadIdx.x;
    int wid  = tid >> 5;
    int lane = tid & 31;
    int nodeBase = blockIdx.x * 128;

    int mwarp = (wid & 1) * 64;     // warp M offset
    int nwarp = (wid >> 1) * 32;    // warp N offset
    int r  = lane >> 2;             // 0..7 groupID
    int c2 = (lane & 3) * 2;        // 0,2,4,6

    if (tid < FDIM) sBias[tid] = bias[tid];

    float acc[4][4][4];             // [mt][nt][frag]
    #pragma unroll
    for (int mt = 0; mt < 4; mt++)
        #pragma unroll
        for (int nt = 0; nt < 4; nt++)
            #pragma unroll
            for (int q = 0; q < 4; q++) acc[mt][nt][q] = 0.f;

    #pragma unroll 1
    for (int c = 0; c < 8; c++) {
        // ---- stage A chunk: 128 nodes x 32 k, fp32 -> bf16 hi/lo ----
        const float* srcA = (c < 4) ? (agg + (size_t)c * KCH)
                                    : (xin + (size_t)(c - 4) * KCH);
        #pragma unroll
        for (int i = tid; i < 1024; i += 256) {      // 128 rows x 8 quads
            int n = i >> 3, q = (i & 7) * 4;
            int node = nodeBase + n;
            float4 v = make_float4(0.f, 0.f, 0.f, 0.f);
            if (node < NODES)
                v = *reinterpret_cast<const float4*>(srcA + (size_t)node * FDIM + q);
            __nv_bfloat16 h0 = __float2bfloat16(v.x), h1 = __float2bfloat16(v.y);
            __nv_bfloat16 h2 = __float2bfloat16(v.z), h3 = __float2bfloat16(v.w);
            __nv_bfloat16 l0 = __float2bfloat16(v.x - __bfloat162float(h0));
            __nv_bfloat16 l1 = __float2bfloat16(v.y - __bfloat162float(h1));
            __nv_bfloat16 l2 = __float2bfloat16(v.z - __bfloat162float(h2));
            __nv_bfloat16 l3 = __float2bfloat16(v.w - __bfloat162float(h3));
            uint32_t* ph = reinterpret_cast<uint32_t*>(&sAhi[n][q]);
            uint32_t* pl = reinterpret_cast<uint32_t*>(&sAlo[n][q]);
            ph[0] = (uint32_t)__bfloat16_as_ushort(h0) | ((uint32_t)__bfloat16_as_ushort(h1) << 16);
            ph[1] = (uint32_t)__bfloat16_as_ushort(h2) | ((uint32_t)__bfloat16_as_ushort(h3) << 16);
            pl[0] = (uint32_t)__bfloat16_as_ushort(l0) | ((uint32_t)__bfloat16_as_ushort(l1) << 16);
            pl[1] = (uint32_t)__bfloat16_as_ushort(l2) | ((uint32_t)__bfloat16_as_ushort(l3) << 16);
        }
        // ---- stage B chunk: 128 f x 32 k from prepped images ----
        #pragma unroll
        for (int i = tid; i < 1024; i += 256) {
            int f = i >> 3, q = (i & 7) * 4;
            const uint32_t* gh = reinterpret_cast<const uint32_t*>(&g_Bhi[layer][f][c * KCH + q]);
            const uint32_t* gl = reinterpret_cast<const uint32_t*>(&g_Blo[layer][f][c * KCH + q]);
            uint32_t* ph = reinterpret_cast<uint32_t*>(&sBhi[f][q]);
            uint32_t* pl = reinterpret_cast<uint32_t*>(&sBlo[f][q]);
            ph[0] = gh[0]; ph[1] = gh[1];
            pl[0] = gl[0]; pl[1] = gl[1];
        }
        __syncthreads();

        // ---- MMA: 2 k16 steps x 3 passes (hh, hl, lh) ----
        #pragma unroll
        for (int ks = 0; ks < 2; ks++) {
            int kb = ks * 16;
            #pragma unroll
            for (int pass = 0; pass < 3; pass++) {
                const __nv_bfloat16 (*A)[APIT] = (pass == 2) ? sAlo : sAhi;
                const __nv_bfloat16 (*B)[APIT] = (pass == 1) ? sBlo : sBhi;

                uint32_t bf[4][2];
                #pragma unroll
                for (int nt = 0; nt < 4; nt++) {
                    int n = nwarp + nt * 8 + r;
                    bf[nt][0] = *reinterpret_cast<const uint32_t*>(&B[n][kb + c2]);
                    bf[nt][1] = *reinterpret_cast<const uint32_t*>(&B[n][kb + c2 + 8]);
                }
                #pragma unroll
                for (int mt = 0; mt < 4; mt++) {
                    int m = mwarp + mt * 16;
                    uint32_t af[4];
                    af[0] = *reinterpret_cast<const uint32_t*>(&A[m + r][kb + c2]);
                    af[1] = *reinterpret_cast<const uint32_t*>(&A[m + r + 8][kb + c2]);
                    af[2] = *reinterpret_cast<const uint32_t*>(&A[m + r][kb + c2 + 8]);
                    af[3] = *reinterpret_cast<const uint32_t*>(&A[m + r + 8][kb + c2 + 8]);
                    #pragma unroll
                    for (int nt = 0; nt < 4; nt++)
                        mma16816(acc[mt][nt], af, bf[nt]);
                }
            }
        }
        __syncthreads();
    }

    // ---- epilogue: bias + relu, float2 stores ----
    #pragma unroll
    for (int mt = 0; mt < 4; mt++) {
        int m0 = mwarp + mt * 16 + r;
        #pragma unroll
        for (int half = 0; half < 2; half++) {       // rows r, r+8
            int node = nodeBase + m0 + half * 8;
            if (node >= NODES) continue;
            float* op = out + (size_t)node * FDIM;
            #pragma unroll
            for (int nt = 0; nt < 4; nt++) {
                int n = nwarp + nt * 8 + c2;
                float2 o;
                o.x = fmaxf(acc[mt][nt][half * 2 + 0] + sBias[n],     0.f);
                o.y = fmaxf(acc[mt][nt][half * 2 + 1] + sBias[n + 1], 0.f);
                *reinterpret_cast<float2*>(op + n) = o;
            }
        }
    }
}

// ---------------------------------------------------------------------------
// CSR build (unchanged from R3)
// ---------------------------------------------------------------------------
__global__ void __launch_bounds__(256) hist_kernel(
    const int* __restrict__ dst, int* __restrict__ deg, int E)
{
    int e = blockIdx.x * blockDim.x + threadIdx.x;
    if (e < E) atomicAdd(&deg[__ldg(dst + e)], 1);
}

__global__ void __launch_bounds__(1024) scan_kernel(
    const int* __restrict__ deg, int* __restrict__ off, int n)
{
    __shared__ int wsum[32];
    __shared__ int blocktot;
    int tid = threadIdx.x, lane = tid & 31, wid = tid >> 5;
    int running = 0;

    for (int base = 0; base < n; base += 1024) {
        int idx = base + tid;
        int v = (idx < n) ? deg[idx] : 0;
        int s = v;
        #pragma unroll
        for (int o = 1; o < 32; o <<= 1) {
            int t = __shfl_up_sync(0xffffffffu, s, o);
            if (lane >= o) s += t;
        }
        if (lane == 31) wsum[wid] = s;
        __syncthreads();
        if (wid == 0) {
            int ws = wsum[lane];
            int ss = ws;
            #pragma unroll
            for (int o = 1; o < 32; o <<= 1) {
                int t = __shfl_up_sync(0xffffffffu, ss, o);
                if (lane >= o) ss += t;
            }
            if (lane == 31) blocktot = ss;
            wsum[lane] = ss - ws;
        }
        __syncthreads();
        int excl = running + wsum[wid] + (s - v);
        if (idx < n) off[idx] = excl;
        running += blocktot;
        __syncthreads();
    }
    if (tid == 0) off[n] = running;
}

__global__ void __launch_bounds__(256) fill_kernel(
    const int* __restrict__ src, const int* __restrict__ dst,
    const int* __restrict__ off, int* __restrict__ cursor,
    int* __restrict__ csr, int E)
{
    int e = blockIdx.x * blockDim.x + threadIdx.x;
    if (e >= E) return;
    int d = __ldg(dst + e);
    int pos = atomicAdd(&cursor[d], 1);
    csr[__ldg(off + d) + pos] = __ldg(src + e);
}

// ---------------------------------------------------------------------------
// Gather aggregation (unchanged from R3)
// ---------------------------------------------------------------------------
__global__ void __launch_bounds__(256) gather_kernel(
    const float* __restrict__ x,
    const int* __restrict__ off, const int* __restrict__ csr,
    float* __restrict__ agg)
{
    int node = (blockIdx.x * blockDim.x + threadIdx.x) >> 5;
    int lane = threadIdx.x & 31;
    if (node >= NODES) return;
    int lo = __ldg(off + node), hi = __ldg(off + node + 1);

    float4 a = make_float4(0.f, 0.f, 0.f, 0.f);
    int i = lo;
    for (; i + 1 < hi; i += 2) {
        int s0 = __ldg(csr + i);
        int s1 = __ldg(csr + i + 1);
        float4 v0 = *reinterpret_cast<const float4*>(x + (size_t)s0 * FDIM + lane * 4);
        float4 v1 = *reinterpret_cast<const float4*>(x + (size_t)s1 * FDIM + lane * 4);
        a.x += v0.x + v1.x; a.y += v0.y + v1.y;
        a.z += v0.z + v1.z; a.w += v0.w + v1.w;
    }
    if (i < hi) {
        int s0 = __ldg(csr + i);
        float4 v0 = *reinterpret_cast<const float4*>(x + (size_t)s0 * FDIM + lane * 4);
        a.x += v0.x; a.y += v0.y; a.z += v0.z; a.w += v0.w;
    }
    *reinterpret_cast<float4*>(agg + (size_t)node * FDIM + lane * 4) = a;
}

// ---------------------------------------------------------------------------
// Classifier (unchanged from R3)
// ---------------------------------------------------------------------------
__global__ void __launch_bounds__(128) cls_kernel(
    const float* __restrict__ x1, const float* __restrict__ x2,
    const float* __restrict__ Wlin, const float* __restrict__ blin,
    float* __restrict__ out, int nGroupsStride)
{
    __shared__ float sW[2 * FDIM * NCLS];
    __shared__ float sb[NCLS];
    __shared__ float sH[4][4][2 * FDIM];

    int tid = threadIdx.x;
    for (int i = tid; i < 2 * FDIM * NCLS; i += 128) sW[i] = Wlin[i];
    if (tid < NCLS) sb[tid] = blin[tid];
    __syncthreads();

    int wid  = tid >> 5;
    int lane = tid & 31;
    int l8   = lane & 7;
    float bias0 = sb[lane];
    float bias1 = sb[32 + l8];

    const int nGroups = (NODES + 3) / 4;
    for (int g = blockIdx.x * 4 + wid; g < nGroups; g += nGroupsStride) {
        int n0 = g * 4;
        #pragma unroll
        for (int j = 0; j < 4; j++) {
            int node = n0 + j; if (node >= NODES) node = NODES - 1;
            reinterpret_cast<float4*>(sH[wid][j])[lane] =
                reinterpret_cast<const float4*>(x1 + (size_t)node * FDIM)[lane];
            reinterpret_cast<float4*>(sH[wid][j])[32 + lane] =
                reinterpret_cast<const float4*>(x2 + (size_t)node * FDIM)[lane];
        }
        __syncwarp();

        float v0[4], v1[4];
        #pragma unroll
        for (int j = 0; j < 4; j++) { v0[j] = bias0; v1[j] = bias1; }

        #pragma unroll 4
        for (int k = 0; k < 2 * FDIM; k++) {
            float w0 = sW[k * NCLS + lane];
            float w1 = sW[k * NCLS + 32 + l8];
            #pragma unroll
            for (int j = 0; j < 4; j++) {
                float h = sH[wid][j][k];
                v0[j] = fmaf(h, w0, v0[j]);
                v1[j] = fmaf(h, w1, v1[j]);
            }
        }

        #pragma unroll
        for (int j = 0; j < 4; j++) {
            int node = n0 + j;
            float m = fmaxf(v0[j], v1[j]);
            #pragma unroll
            for (int off = 16; off; off >>= 1)
                m = fmaxf(m, __shfl_xor_sync(0xffffffffu, m, off));
            float s = __expf(v0[j] - m) + ((lane < 8) ? __expf(v1[j] - m) : 0.f);
            #pragma unroll
            for (int off = 16; off; off >>= 1)
                s += __shfl_xor_sync(0xffffffffu, s, off);
            float lse = m + __logf(s);
            if (node < NODES) {
                out[(size_t)node * NCLS + lane] = v0[j] - lse;
                if (lane < 8) out[(size_t)node * NCLS + 32 + lane] = v1[j] - lse;
            }
        }
        __syncwarp();
    }
}

// ---------------------------------------------------------------------------
extern "C" void kernel_launch(void* const* d_in, const int* in_sizes, int n_in,
                              void* d_out, int out_size)
{
    const float* x      = (const float*)d_in[0];
    const int*   eidx   = (const int*)  d_in[1];
    const float* Wrel1  = (const float*)d_in[2];
    const float* b1     = (const float*)d_in[3];
    const float* Wroot1 = (const float*)d_in[4];
    const float* Wrel2  = (const float*)d_in[5];
    const float* b2     = (const float*)d_in[6];
    const float* Wroot2 = (const float*)d_in[7];
    const float* Wlin   = (const float*)d_in[8];
    const float* blin   = (const float*)d_in[9];
    float* out = (float*)d_out;

    int E = in_sizes[1] / 2;
    const int* src = eidx;
    const int* dst = eidx + E;

    float *agg, *x1, *x2;
    int *deg, *cursor, *off, *csr;
    cudaGetSymbolAddress((void**)&agg,    g_agg);
    cudaGetSymbolAddress((void**)&x1,     g_x1);
    cudaGetSymbolAddress((void**)&x2,     g_x2);
    cudaGetSymbolAddress((void**)&deg,    g_deg);
    cudaGetSymbolAddress((void**)&cursor, g_cursor);
    cudaGetSymbolAddress((void**)&off,    g_off);
    cudaGetSymbolAddress((void**)&csr,    g_csr);

    int eblocks = (E + 255) / 256;
    int gblocks = (NODES * 32 + 255) / 256;
    int cblocks = (NODES + 127) / 128;

    // --- weight prep + CSR build ---
    prep_kernel<<<256, 256>>>(Wrel1, Wroot1, Wrel2, Wroot2);
    cudaMemsetAsync(deg,    0, NODES * sizeof(int), 0);
    cudaMemsetAsync(cursor, 0, NODES * sizeof(int), 0);
    hist_kernel<<<eblocks, 256>>>(dst, deg, E);
    scan_kernel<<<1, 1024>>>(deg, off, NODES);
    fill_kernel<<<eblocks, 256>>>(src, dst, off, cursor, csr, E);

    // --- Layer 1 ---
    gather_kernel<<<gblocks, 256>>>(x, off, csr, agg);
    conv_kernel<<<cblocks, 256>>>(x, agg, b1, x1, 0);

    // --- Layer 2 ---
    gather_kernel<<<gblocks, 256>>>(x1, off, csr, agg);
    conv_kernel<<<cblocks, 256>>>(x1, agg, b2, x2, 1);

    // --- Classifier + log_softmax ---
    int clsBlocks = 592;
    cls_kernel<<<clsBlocks, 128>>>(x1, x2, Wlin, blin, out, clsBlocks * 4);
}